// round 1
// baseline (speedup 1.0000x reference)
#include <cuda_runtime.h>

// Problem constants (fixed by the dataset)
#define NMAX 50000
#define EMAX 640000

// Scratch (allocation-free rule: __device__ globals)
__device__ float g_dinv[NMAX];          // deg -> rsqrt(deg) in place
__device__ float g_norm[EMAX];          // per-edge normalization
__device__ float g_h[NMAX * 128];       // GEMM output (pre-aggregation)
__device__ float g_agg[NMAX * 128];     // aggregation buffer (init + scatter)
__device__ float g_h3[NMAX * 40];       // layer-3 GEMM output

// ---------------------------------------------------------------------------
// Degree / normalization precompute
// ---------------------------------------------------------------------------
__global__ void deg_init_kernel(float* deg, int n) {
    int i = blockIdx.x * blockDim.x + threadIdx.x;
    if (i < n) deg[i] = 1.0f;  // self-loop weight
}

__global__ void deg_acc_kernel(const int* __restrict__ dst,
                               const float* __restrict__ ew,
                               float* deg, int e) {
    int i = blockIdx.x * blockDim.x + threadIdx.x;
    if (i < e) atomicAdd(deg + dst[i], ew[i]);
}

__global__ void dinv_kernel(float* deg, int n) {
    int i = blockIdx.x * blockDim.x + threadIdx.x;
    if (i < n) deg[i] = rsqrtf(deg[i]);  // deg >= 1 always
}

__global__ void norm_kernel(const int* __restrict__ src,
                            const int* __restrict__ dst,
                            const float* __restrict__ ew,
                            const float* __restrict__ dinv,
                            float* __restrict__ nrm, int e) {
    int i = blockIdx.x * blockDim.x + threadIdx.x;
    if (i < e) nrm[i] = dinv[src[i]] * ew[i] * dinv[dst[i]];
}

// ---------------------------------------------------------------------------
// GEMM: [n,128] @ [128,128] -> writes H (raw) and AGG init = H*dinv^2 + bias
// Optional ReLU applied to the A operand on load (fuses previous layer's relu).
// BM=128, BN=128, BK=16, 256 threads, 8x8 microtile.
// ---------------------------------------------------------------------------
template <bool RELU_IN>
__global__ void __launch_bounds__(256, 2)
gemm128_kernel(const float* __restrict__ A,
               const float* __restrict__ W,
               const float* __restrict__ bias,
               const float* __restrict__ dinv,
               float* __restrict__ Hout,
               float* __restrict__ AggOut,
               int n) {
    __shared__ float As[16][128];  // transposed: As[k][m]
    __shared__ float Bs[16][128];  // Bs[k][n]

    const int tid = threadIdx.x;
    const int tx = tid & 15;        // 0..15 -> N dim
    const int ty = tid >> 4;        // 0..15 -> M dim
    const int rb = blockIdx.x * 128;

    float acc[8][8];
#pragma unroll
    for (int i = 0; i < 8; i++)
#pragma unroll
        for (int j = 0; j < 8; j++) acc[i][j] = 0.0f;

    for (int k0 = 0; k0 < 128; k0 += 16) {
        // Load A tile: 128 rows x 16 cols = 512 float4, 2 per thread
#pragma unroll
        for (int l = 0; l < 2; l++) {
            int f = tid + l * 256;          // 0..511
            int row = f >> 2;               // 0..127
            int c4 = (f & 3) * 4;           // 0,4,8,12
            float4 v = make_float4(0.f, 0.f, 0.f, 0.f);
            int gr = rb + row;
            if (gr < n) v = *(const float4*)(A + (size_t)gr * 128 + k0 + c4);
            if (RELU_IN) {
                v.x = fmaxf(v.x, 0.f); v.y = fmaxf(v.y, 0.f);
                v.z = fmaxf(v.z, 0.f); v.w = fmaxf(v.w, 0.f);
            }
            As[c4 + 0][row] = v.x;
            As[c4 + 1][row] = v.y;
            As[c4 + 2][row] = v.z;
            As[c4 + 3][row] = v.w;
        }
        // Load B tile: 16 rows x 128 cols = 512 float4, 2 per thread
#pragma unroll
        for (int l = 0; l < 2; l++) {
            int f = tid + l * 256;
            int kr = f >> 5;                // 0..15
            int c = (f & 31) * 4;           // 0..124
            float4 v = *(const float4*)(W + (size_t)(k0 + kr) * 128 + c);
            *(float4*)&Bs[kr][c] = v;
        }
        __syncthreads();

#pragma unroll
        for (int k = 0; k < 16; k++) {
            float4 a0 = *(const float4*)&As[k][ty * 8];
            float4 a1 = *(const float4*)&As[k][ty * 8 + 4];
            float4 b0 = *(const float4*)&Bs[k][tx * 8];
            float4 b1 = *(const float4*)&Bs[k][tx * 8 + 4];
            float a[8] = {a0.x, a0.y, a0.z, a0.w, a1.x, a1.y, a1.z, a1.w};
            float b[8] = {b0.x, b0.y, b0.z, b0.w, b1.x, b1.y, b1.z, b1.w};
#pragma unroll
            for (int i = 0; i < 8; i++)
#pragma unroll
                for (int j = 0; j < 8; j++)
                    acc[i][j] = fmaf(a[i], b[j], acc[i][j]);
        }
        __syncthreads();
    }

    // Epilogue: write H, and AGG init = H * dinv^2 + bias (self-loop + bias)
#pragma unroll
    for (int i = 0; i < 8; i++) {
        int row = rb + ty * 8 + i;
        if (row >= n) break;
        float sl = dinv[row];
        sl = sl * sl;
#pragma unroll
        for (int j = 0; j < 8; j += 4) {
            int col = tx * 8 + j;
            float4 hv = make_float4(acc[i][j], acc[i][j + 1], acc[i][j + 2], acc[i][j + 3]);
            *(float4*)(Hout + (size_t)row * 128 + col) = hv;
            float4 bv = *(const float4*)(bias + col);
            float4 av;
            av.x = fmaf(hv.x, sl, bv.x);
            av.y = fmaf(hv.y, sl, bv.y);
            av.z = fmaf(hv.z, sl, bv.z);
            av.w = fmaf(hv.w, sl, bv.w);
            *(float4*)(AggOut + (size_t)row * 128 + col) = av;
        }
    }
}

// ---------------------------------------------------------------------------
// Edge scatter (128 features): one warp per edge, vectorized red.global.add
// ---------------------------------------------------------------------------
__global__ void __launch_bounds__(256)
scatter128_kernel(const float* __restrict__ h,
                  const int* __restrict__ src,
                  const int* __restrict__ dst,
                  const float* __restrict__ nrm,
                  float* __restrict__ agg,
                  int e) {
    int warp = (blockIdx.x * blockDim.x + threadIdx.x) >> 5;
    int lane = threadIdx.x & 31;
    if (warp >= e) return;
    int s = src[warp];
    int d = dst[warp];
    float nm = nrm[warp];
    float4 v = *(const float4*)(h + (size_t)s * 128 + lane * 4);
    float rx = v.x * nm, ry = v.y * nm, rz = v.z * nm, rw = v.w * nm;
    float* p = agg + (size_t)d * 128 + lane * 4;
    asm volatile("red.global.add.v4.f32 [%0], {%1, %2, %3, %4};"
                 :: "l"(p), "f"(rx), "f"(ry), "f"(rz), "f"(rw)
                 : "memory");
}

// ---------------------------------------------------------------------------
// Layer-3 GEMM: [n,128] @ [128,40], ReLU on A load.
// Writes H3 and Out init = H3*dinv^2 + bias. 64 rows/block, 128 threads.
// Dynamic smem: xs[64*129] + ws[128*40].
// ---------------------------------------------------------------------------
__global__ void __launch_bounds__(128)
gemm40_kernel(const float* __restrict__ A,
              const float* __restrict__ W,
              const float* __restrict__ bias,
              const float* __restrict__ dinv,
              float* __restrict__ Hout,
              float* __restrict__ Out,
              int n) {
    extern __shared__ float sm[];
    float* xs = sm;                 // 64 rows, stride 129 (conflict-free)
    float* ws = sm + 64 * 129;      // 128*40 flat

    const int tid = threadIdx.x;
    const int rb = blockIdx.x * 64;

    // Load W3 (5120 floats) with float4
    for (int l = tid * 4; l < 128 * 40; l += 128 * 4)
        *(float4*)(ws + l) = *(const float4*)(W + l);

    // Load x tile with relu: 64 rows x 128 cols = 2048 float4
    for (int f = tid; f < 2048; f += 128) {
        int row = f >> 5;
        int c = (f & 31) * 4;
        float4 v = make_float4(0.f, 0.f, 0.f, 0.f);
        int gr = rb + row;
        if (gr < n) v = *(const float4*)(A + (size_t)gr * 128 + c);
        float* xr = xs + row * 129 + c;
        xr[0] = fmaxf(v.x, 0.f);
        xr[1] = fmaxf(v.y, 0.f);
        xr[2] = fmaxf(v.z, 0.f);
        xr[3] = fmaxf(v.w, 0.f);
    }
    __syncthreads();

    const int tc = tid & 7;     // col group: cols tc + 8j, j<5
    const int tr = tid >> 3;    // 0..15 -> rows tr*4 .. tr*4+3
    float acc[4][5];
#pragma unroll
    for (int r = 0; r < 4; r++)
#pragma unroll
        for (int j = 0; j < 5; j++) acc[r][j] = 0.0f;

#pragma unroll 4
    for (int k = 0; k < 128; k++) {
        float w[5];
#pragma unroll
        for (int j = 0; j < 5; j++) w[j] = ws[k * 40 + tc + 8 * j];
#pragma unroll
        for (int r = 0; r < 4; r++) {
            float a = xs[(tr * 4 + r) * 129 + k];
#pragma unroll
            for (int j = 0; j < 5; j++) acc[r][j] = fmaf(a, w[j], acc[r][j]);
        }
    }

#pragma unroll
    for (int r = 0; r < 4; r++) {
        int row = rb + tr * 4 + r;
        if (row >= n) break;
        float sl = dinv[row];
        sl = sl * sl;
#pragma unroll
        for (int j = 0; j < 5; j++) {
            int c = tc + 8 * j;
            float v = acc[r][j];
            Hout[(size_t)row * 40 + c] = v;
            Out[(size_t)row * 40 + c] = fmaf(v, sl, bias[c]);
        }
    }
}

// ---------------------------------------------------------------------------
// Edge scatter (40 features): 10 float4 chunks per edge
// ---------------------------------------------------------------------------
__global__ void __launch_bounds__(256)
scatter40_kernel(const float* __restrict__ h,
                 const int* __restrict__ src,
                 const int* __restrict__ dst,
                 const float* __restrict__ nrm,
                 float* __restrict__ out,
                 int e) {
    long long idx = (long long)blockIdx.x * blockDim.x + threadIdx.x;
    long long total = (long long)e * 10;
    if (idx >= total) return;
    int ed = (int)(idx / 10);
    int c = (int)(idx - (long long)ed * 10);
    int s = src[ed];
    int d = dst[ed];
    float nm = nrm[ed];
    float4 v = *(const float4*)(h + (size_t)s * 40 + c * 4);
    float rx = v.x * nm, ry = v.y * nm, rz = v.z * nm, rw = v.w * nm;
    float* p = out + (size_t)d * 40 + c * 4;
    asm volatile("red.global.add.v4.f32 [%0], {%1, %2, %3, %4};"
                 :: "l"(p), "f"(rx), "f"(ry), "f"(rz), "f"(rw)
                 : "memory");
}

// ---------------------------------------------------------------------------
// Launch
// ---------------------------------------------------------------------------
extern "C" void kernel_launch(void* const* d_in, const int* in_sizes, int n_in,
                              void* d_out, int out_size) {
    const float* x  = (const float*)d_in[0];
    const int*   ei = (const int*)d_in[1];
    const float* ew = (const float*)d_in[2];
    const float* W1 = (const float*)d_in[3];
    const float* b1 = (const float*)d_in[4];
    const float* W2 = (const float*)d_in[5];
    const float* b2 = (const float*)d_in[6];
    const float* W3 = (const float*)d_in[7];
    const float* b3 = (const float*)d_in[8];
    float* out = (float*)d_out;

    const int n = in_sizes[0] / 128;       // 50000
    const int e = in_sizes[2];             // 640000
    const int* src = ei;
    const int* dst = ei + e;

    float *dinv, *nrm, *h, *agg, *h3;
    cudaGetSymbolAddress((void**)&dinv, g_dinv);
    cudaGetSymbolAddress((void**)&nrm,  g_norm);
    cudaGetSymbolAddress((void**)&h,    g_h);
    cudaGetSymbolAddress((void**)&agg,  g_agg);
    cudaGetSymbolAddress((void**)&h3,   g_h3);

    const int nb_n = (n + 255) / 256;
    const int nb_e = (e + 255) / 256;

    // Degree + normalization
    deg_init_kernel<<<nb_n, 256>>>(dinv, n);
    deg_acc_kernel<<<nb_e, 256>>>(dst, ew, dinv, e);
    dinv_kernel<<<nb_n, 256>>>(dinv, n);
    norm_kernel<<<nb_e, 256>>>(src, dst, ew, dinv, nrm, e);

    const int gemm_blocks = (n + 127) / 128;
    const int scat_blocks = (e * 32 + 255) / 256;   // one warp per edge

    // Layer 1: h1 = x@W1; agg = h1*dinv^2 + b1 + scatter; (relu deferred)
    gemm128_kernel<false><<<gemm_blocks, 256>>>(x, W1, b1, dinv, h, agg, n);
    scatter128_kernel<<<scat_blocks, 256>>>(h, src, dst, nrm, agg, e);

    // Layer 2: relu fused into A load
    gemm128_kernel<true><<<gemm_blocks, 256>>>(agg, W2, b2, dinv, h, agg, n);
    scatter128_kernel<<<scat_blocks, 256>>>(h, src, dst, nrm, agg, e);

    // Layer 3: relu fused; output written directly to d_out
    static const int g40_smem = (64 * 129 + 128 * 40) * sizeof(float);
    cudaFuncSetAttribute(gemm40_kernel,
                         cudaFuncAttributeMaxDynamicSharedMemorySize, g40_smem);
    gemm40_kernel<<<(n + 63) / 64, 128, g40_smem>>>(agg, W3, b3, dinv, h3, out, n);

    long long s40_threads = (long long)e * 10;
    int s40_blocks = (int)((s40_threads + 255) / 256);
    scatter40_kernel<<<s40_blocks, 256>>>(h3, src, dst, nrm, out, e);
}